// round 2
// baseline (speedup 1.0000x reference)
#include <cuda_runtime.h>
#include <math.h>

// Problem dims
#define GG 32          // B*H
#define NV 1024        // nodes
#define FF 128         // features = hidden
#define NN (NV*NV)
#define K_TOP 32768    // (N*N) // sqrt(N)
#define NBINS 8192
#define CAP 24576

// ---------------- scratch (device globals; no allocation allowed) ----------------
__device__ unsigned g_hist1[GG*NBINS];
__device__ unsigned g_bin1[GG];
__device__ unsigned g_above[GG];
__device__ unsigned g_cand_cnt[GG];
__device__ unsigned g_cand_bits[GG*CAP];
__device__ unsigned g_cand_idx[GG*CAP];
__device__ unsigned g_thr[GG];
__device__ unsigned g_cut[GG];
__device__ float    g_rowsum[GG*NV];
__device__ float    g_colsum[GG*NV];
__device__ float    g_dinv[GG*NV];
__device__ float    g_y[(size_t)GG*NV*FF];   // y = x @ W  (16 MB)

// ---------------- 1) level-1 histogram over bits>>17 ----------------
__global__ void k_hist(const unsigned* __restrict__ adj) {
    __shared__ unsigned sh[NBINS];
    for (int i = threadIdx.x; i < NBINS; i += 256) sh[i] = 0;
    __syncthreads();
    int g = blockIdx.y;
    int slice = NN / gridDim.x;
    const unsigned* base = adj + (size_t)g * NN + (size_t)blockIdx.x * slice;
    for (int i = threadIdx.x; i < slice; i += 256) {
        unsigned b = base[i];
        atomicAdd(&sh[b >> 17], 1u);
    }
    __syncthreads();
    for (int i = threadIdx.x; i < NBINS; i += 256)
        if (sh[i]) atomicAdd(&g_hist1[g*NBINS + i], sh[i]);
}

// ---------------- 2) find bin containing k-th largest ----------------
__global__ void k_scan() {
    int g = blockIdx.x;
    int t = threadIdx.x;           // 256 threads, 32 bins each
    __shared__ unsigned ts[256];
    __shared__ int s_t;
    __shared__ unsigned s_excl;
    const unsigned* h = g_hist1 + g*NBINS;
    unsigned s = 0;
    for (int b = 0; b < 32; b++) s += h[t*32 + b];
    ts[t] = s;
    __syncthreads();
    if (t == 0) {
        unsigned c = 0;
        s_t = 0; s_excl = 0;
        for (int i = 255; i >= 0; i--) {
            if (c + ts[i] >= K_TOP) { s_t = i; s_excl = c; break; }
            c += ts[i];
        }
    }
    __syncthreads();
    if (t == s_t) {
        unsigned c = s_excl;
        for (int b = 31; b >= 0; b--) {
            unsigned hb = h[t*32 + b];
            if (c + hb >= K_TOP) { g_bin1[g] = t*32 + b; g_above[g] = c; break; }
            c += hb;
        }
    }
}

// ---------------- 3) collect candidates in the threshold bin ----------------
__global__ void k_collect(const unsigned* __restrict__ adj) {
    int g = blockIdx.y;
    unsigned bin1 = g_bin1[g];
    int slice = NN / gridDim.x;
    unsigned start = blockIdx.x * slice;
    const unsigned* base = adj + (size_t)g * NN;
    for (int i = threadIdx.x; i < slice; i += 256) {
        unsigned idx = start + i;
        unsigned b = base[idx];
        if ((b >> 17) == bin1) {
            unsigned p = atomicAdd(&g_cand_cnt[g], 1u);
            if (p < CAP) { g_cand_bits[g*CAP + p] = b; g_cand_idx[g*CAP + p] = idx; }
        }
    }
}

// ---------------- 4) exact threshold bits + tie cutoff index ----------------
__global__ void k_select() {
    int g = blockIdx.x;
    int t = threadIdx.x;  // 512 threads
    unsigned n = min(g_cand_cnt[g], (unsigned)CAP);
    unsigned r = K_TOP - g_above[g];   // rank (1-based, largest-first) within the bin
    __shared__ unsigned hA[512];
    __shared__ unsigned selA, aboveA, selB, aboveB;
    __shared__ unsigned eqIdx[64];
    __shared__ unsigned eqCnt;
    const unsigned* cb = g_cand_bits + g*CAP;
    const unsigned* ci = g_cand_idx + g*CAP;

    for (int i = t; i < 512; i += 512) hA[i] = 0;
    if (t == 0) eqCnt = 0;
    __syncthreads();
    for (unsigned i = t; i < n; i += 512) atomicAdd(&hA[(cb[i] >> 8) & 0x1FF], 1u);
    __syncthreads();
    if (t == 0) {
        unsigned c = 0; selA = 0; aboveA = 0;
        for (int b = 511; b >= 0; b--) {
            if (c + hA[b] >= r) { selA = b; aboveA = c; break; }
            c += hA[b];
        }
    }
    __syncthreads();
    unsigned sA = selA;
    for (int i = t; i < 256; i += 512) hA[i] = 0;
    __syncthreads();
    for (unsigned i = t; i < n; i += 512) {
        unsigned b = cb[i];
        if (((b >> 8) & 0x1FF) == sA) atomicAdd(&hA[b & 0xFF], 1u);
    }
    __syncthreads();
    if (t == 0) {
        unsigned r2 = r - aboveA;
        unsigned c = 0; selB = 0; aboveB = 0;
        for (int b = 255; b >= 0; b--) {
            if (c + hA[b] >= r2) { selB = b; aboveB = c; break; }
            c += hA[b];
        }
    }
    __syncthreads();
    unsigned thr = (g_bin1[g] << 17) | (sA << 8) | selB;
    for (unsigned i = t; i < n; i += 512) {
        if (cb[i] == thr) {
            unsigned p = atomicAdd(&eqCnt, 1u);
            if (p < 64) eqIdx[p] = ci[i];
        }
    }
    __syncthreads();
    if (t == 0) {
        unsigned need = (r - aboveA) - aboveB;   // #ties to keep (>=1)
        unsigned m = min(eqCnt, 64u);
        unsigned cut = 0xFFFFFFFFu;
        if (need < m) {
            // need-th smallest flat index among the ties (top_k keeps lowest indices)
            for (unsigned s = 0; s < need; s++) {
                unsigned best = 0xFFFFFFFFu; int bi = -1;
                for (unsigned i = 0; i < m; i++)
                    if (eqIdx[i] < best) { best = eqIdx[i]; bi = (int)i; }
                eqIdx[bi] = 0xFFFFFFFFu;
                cut = best;
            }
        }
        g_thr[g] = thr; g_cut[g] = cut;
    }
}

__device__ __forceinline__ bool keptf(unsigned bits, unsigned flat, unsigned thr, unsigned cut) {
    return (bits > thr) || (bits == thr && flat <= cut);
}

// ---------------- 5) degree: rowsum + colsum of kept entries ----------------
__global__ void k_deg(const float* __restrict__ adj) {
    int g = blockIdx.y;
    int warp = threadIdx.x >> 5, lane = threadIdx.x & 31;
    int row = blockIdx.x * 8 + warp;
    unsigned thr = g_thr[g], cut = g_cut[g];
    const float* a = adj + (size_t)g * NN + (size_t)row * NV;
    unsigned rowbase = (unsigned)row * NV;
    float rs = 0.f;
    for (int j = lane; j < NV; j += 32) {
        float v = a[j];
        unsigned b = __float_as_uint(v);
        if (keptf(b, rowbase + j, thr, cut)) {
            rs += v;
            atomicAdd(&g_colsum[g*NV + j], v);
        }
    }
    #pragma unroll
    for (int o = 16; o; o >>= 1) rs += __shfl_down_sync(0xFFFFFFFFu, rs, o);
    if (lane == 0) g_rowsum[g*NV + row] = rs;
}

__global__ void k_dinv() {
    int i = blockIdx.x * 256 + threadIdx.x;
    if (i < GG*NV) {
        float d = 0.5f * (g_rowsum[i] + g_colsum[i]);
        g_dinv[i] = d > 0.f ? rsqrtf(d) : 0.f;
    }
}

// ---------------- 6) norm_adj = dinv_i * 0.5*(kept_ij + kept_ji) * dinv_j ----------------
__global__ void k_norm(const float* __restrict__ adj, float* __restrict__ outA) {
    int g = blockIdx.z;
    int i0 = blockIdx.y * 32, j0 = blockIdx.x * 32;
    __shared__ float At[32][33];
    int tx = threadIdx.x, ty = threadIdx.y;   // 32 x 8
    const float* a = adj + (size_t)g * NN;
    for (int rr = ty; rr < 32; rr += 8)
        At[rr][tx] = a[(size_t)(j0 + rr) * NV + i0 + tx];
    __syncthreads();
    unsigned thr = g_thr[g], cut = g_cut[g];
    float dj = g_dinv[g*NV + j0 + tx];
    #pragma unroll
    for (int s = 0; s < 4; s++) {
        int ii = ty + 8 * s;
        int i = i0 + ii, j = j0 + tx;
        float vij = a[(size_t)i * NV + j];
        float vji = At[tx][ii];
        unsigned bij = __float_as_uint(vij), bji = __float_as_uint(vji);
        float sum = 0.f;
        if (keptf(bij, (unsigned)(i*NV + j), thr, cut)) sum += vij;
        if (keptf(bji, (unsigned)(j*NV + i), thr, cut)) sum += vji;
        float nm = 0.5f * sum * g_dinv[g*NV + i] * dj;
        outA[(size_t)g * NN + (size_t)i * NV + j] = nm;
    }
}

// ---------------- 7) y = x @ W  (flattened [G*N, F] @ [F, F]) ----------------
__global__ void k_y(const float* __restrict__ x, const float* __restrict__ Wm) {
    __shared__ float Xs[32][FF];
    int blk = blockIdx.x;           // 32 rows per block
    int t = threadIdx.x;            // 128 threads = output column
    const float* xr = x + (size_t)blk * 32 * FF;
    for (int i = t; i < 32 * FF; i += 128) Xs[i / FF][i % FF] = xr[i];
    __syncthreads();
    float acc[32];
    #pragma unroll
    for (int r = 0; r < 32; r++) acc[r] = 0.f;
    for (int k = 0; k < FF; k++) {
        float w = Wm[k * FF + t];
        #pragma unroll
        for (int r = 0; r < 32; r++) acc[r] += Xs[r][k] * w;
    }
    float* yo = g_y + (size_t)blk * 32 * FF;
    #pragma unroll
    for (int r = 0; r < 32; r++) yo[r * FF + t] = acc[r];
}

// ---------------- 8) z = norm @ y ; h = gelu(z + y + b) ----------------
__global__ void __launch_bounds__(256) k_z(const float* __restrict__ outA,
                                           const float* __restrict__ bvec,
                                           float* __restrict__ outH) {
    int g = blockIdx.y;
    int m0 = blockIdx.x * 64;
    const float* A  = outA + (size_t)g * NN;
    const float* Bm = g_y  + (size_t)g * NV * FF;
    __shared__ float As[16][64];
    __shared__ float Bs[16][128];
    int t  = threadIdx.x;
    int tx = t & 15, ty = t >> 4;
    float acc[4][8];
    #pragma unroll
    for (int r = 0; r < 4; r++)
        #pragma unroll
        for (int c = 0; c < 8; c++) acc[r][c] = 0.f;

    int mA = t >> 2, kq = t & 3;
    for (int k0 = 0; k0 < NV; k0 += 16) {
        float4 av = *(const float4*)&A[(size_t)(m0 + mA) * NV + k0 + kq * 4];
        As[kq*4+0][mA] = av.x; As[kq*4+1][mA] = av.y;
        As[kq*4+2][mA] = av.z; As[kq*4+3][mA] = av.w;
        #pragma unroll
        for (int q = t; q < 512; q += 256) {
            int kk = q >> 5, nn = (q & 31) * 4;
            *(float4*)&Bs[kk][nn] = *(const float4*)&Bm[(size_t)(k0 + kk) * FF + nn];
        }
        __syncthreads();
        #pragma unroll
        for (int k = 0; k < 16; k++) {
            float4 a4 = *(float4*)&As[k][ty * 4];
            float4 b0 = *(float4*)&Bs[k][tx * 8];
            float4 b1 = *(float4*)&Bs[k][tx * 8 + 4];
            float ar[4] = {a4.x, a4.y, a4.z, a4.w};
            float br[8] = {b0.x, b0.y, b0.z, b0.w, b1.x, b1.y, b1.z, b1.w};
            #pragma unroll
            for (int r = 0; r < 4; r++)
                #pragma unroll
                for (int c = 0; c < 8; c++)
                    acc[r][c] += ar[r] * br[c];
        }
        __syncthreads();
    }
    #pragma unroll
    for (int r = 0; r < 4; r++) {
        int i = m0 + ty * 4 + r;
        #pragma unroll
        for (int c = 0; c < 8; c++) {
            int n = tx * 8 + c;
            float z = acc[r][c] + Bm[(size_t)i * FF + n] + bvec[n];
            float h = 0.5f * z * (1.f + erff(z * 0.70710678118654752f));
            outH[((size_t)g * NV + i) * FF + n] = h;
        }
    }
}

// ---------------- launcher ----------------
extern "C" void kernel_launch(void* const* d_in, const int* in_sizes, int n_in,
                              void* d_out, int out_size) {
    const float* x   = (const float*)d_in[0];   // [8,4,1024,128]
    const float* adj = (const float*)d_in[1];   // [8,4,1024,1024]
    const float* Wm  = (const float*)d_in[2];   // [128,128]
    const float* bv  = (const float*)d_in[3];   // [128]
    float* outH = (float*)d_out;                         // gelu output, 4194304 floats
    float* outA = (float*)d_out + (size_t)GG * NV * FF;  // norm_adj copy, 33554432 floats

    void *p_hist, *p_colsum, *p_ccnt;
    cudaGetSymbolAddress(&p_hist, g_hist1);
    cudaGetSymbolAddress(&p_colsum, g_colsum);
    cudaGetSymbolAddress(&p_ccnt, g_cand_cnt);
    cudaMemsetAsync(p_hist, 0, sizeof(unsigned) * GG * NBINS);
    cudaMemsetAsync(p_colsum, 0, sizeof(float) * GG * NV);
    cudaMemsetAsync(p_ccnt, 0, sizeof(unsigned) * GG);

    k_hist<<<dim3(16, GG), 256>>>((const unsigned*)adj);
    k_scan<<<GG, 256>>>();
    k_collect<<<dim3(32, GG), 256>>>((const unsigned*)adj);
    k_select<<<GG, 512>>>();
    k_deg<<<dim3(NV / 8, GG), 256>>>(adj);
    k_dinv<<<(GG * NV + 255) / 256, 256>>>();
    k_norm<<<dim3(NV / 32, NV / 32, GG), dim3(32, 8)>>>(adj, outA);
    k_y<<<(GG * NV) / 32, 128>>>(x, Wm);
    k_z<<<dim3(NV / 64, GG), 256>>>(outA, bv, outH);
}

// round 4
// speedup vs baseline: 1.1383x; 1.1383x over previous
#include <cuda_runtime.h>
#include <math.h>

// Problem dims
#define GG 32          // B*H
#define NV 1024        // nodes
#define FF 128         // features = hidden
#define NN (NV*NV)
#define K_TOP 32768    // (N*N) // sqrt(N)
#define NBINS 8192
#define CAP 24576
#define RCAP 128       // padded CSR slots per row (avg ~64, ~8sd margin)

// ---------------- scratch (device globals; no allocation allowed) ----------------
__device__ unsigned g_hist1[GG*NBINS];
__device__ unsigned g_bin1[GG];
__device__ unsigned g_above[GG];
__device__ unsigned g_cand_cnt[GG];
__device__ unsigned g_cand_bits[GG*CAP];
__device__ unsigned g_cand_idx[GG*CAP];
__device__ unsigned g_thr[GG];
__device__ unsigned g_cut[GG];
__device__ float    g_rowsum[GG*NV];
__device__ float    g_colsum[GG*NV];
__device__ float    g_dinv[GG*NV];
__device__ float    g_y[(size_t)GG*NV*FF];         // y = x @ W  (16 MB)
__device__ unsigned g_rcnt[GG*NV];                 // nnz per row
__device__ float2   g_csr[(size_t)GG*NV*RCAP];     // (col-as-bits, val) 32 MB

// ---------------- 1) level-1 histogram over bits>>17 ----------------
__global__ void k_hist(const unsigned* __restrict__ adj) {
    __shared__ unsigned sh[NBINS];
    for (int i = threadIdx.x; i < NBINS; i += 256) sh[i] = 0;
    __syncthreads();
    int g = blockIdx.y;
    int slice = NN / gridDim.x;
    const unsigned* base = adj + (size_t)g * NN + (size_t)blockIdx.x * slice;
    for (int i = threadIdx.x; i < slice; i += 256) {
        unsigned b = base[i];
        atomicAdd(&sh[b >> 17], 1u);
    }
    __syncthreads();
    for (int i = threadIdx.x; i < NBINS; i += 256)
        if (sh[i]) atomicAdd(&g_hist1[g*NBINS + i], sh[i]);
}

// ---------------- 2) find bin containing k-th largest ----------------
__global__ void k_scan() {
    int g = blockIdx.x;
    int t = threadIdx.x;           // 256 threads, 32 bins each
    __shared__ unsigned ts[256];
    __shared__ int s_t;
    __shared__ unsigned s_excl;
    const unsigned* h = g_hist1 + g*NBINS;
    unsigned s = 0;
    for (int b = 0; b < 32; b++) s += h[t*32 + b];
    ts[t] = s;
    __syncthreads();
    if (t == 0) {
        unsigned c = 0;
        s_t = 0; s_excl = 0;
        for (int i = 255; i >= 0; i--) {
            if (c + ts[i] >= K_TOP) { s_t = i; s_excl = c; break; }
            c += ts[i];
        }
    }
    __syncthreads();
    if (t == s_t) {
        unsigned c = s_excl;
        for (int b = 31; b >= 0; b--) {
            unsigned hb = h[t*32 + b];
            if (c + hb >= K_TOP) { g_bin1[g] = t*32 + b; g_above[g] = c; break; }
            c += hb;
        }
    }
}

// ---------------- 3) collect candidates in the threshold bin ----------------
__global__ void k_collect(const unsigned* __restrict__ adj) {
    int g = blockIdx.y;
    unsigned bin1 = g_bin1[g];
    int slice = NN / gridDim.x;
    unsigned start = blockIdx.x * slice;
    const unsigned* base = adj + (size_t)g * NN;
    for (int i = threadIdx.x; i < slice; i += 256) {
        unsigned idx = start + i;
        unsigned b = base[idx];
        if ((b >> 17) == bin1) {
            unsigned p = atomicAdd(&g_cand_cnt[g], 1u);
            if (p < CAP) { g_cand_bits[g*CAP + p] = b; g_cand_idx[g*CAP + p] = idx; }
        }
    }
}

// ---------------- 4) exact threshold bits + tie cutoff index ----------------
__global__ void k_select() {
    int g = blockIdx.x;
    int t = threadIdx.x;  // 512 threads
    unsigned n = min(g_cand_cnt[g], (unsigned)CAP);
    unsigned r = K_TOP - g_above[g];   // rank (1-based, largest-first) within the bin
    __shared__ unsigned hA[512];
    __shared__ unsigned selA, aboveA, selB, aboveB;
    __shared__ unsigned eqIdx[64];
    __shared__ unsigned eqCnt;
    const unsigned* cb = g_cand_bits + g*CAP;
    const unsigned* ci = g_cand_idx + g*CAP;

    for (int i = t; i < 512; i += 512) hA[i] = 0;
    if (t == 0) eqCnt = 0;
    __syncthreads();
    for (unsigned i = t; i < n; i += 512) atomicAdd(&hA[(cb[i] >> 8) & 0x1FF], 1u);
    __syncthreads();
    if (t == 0) {
        unsigned c = 0; selA = 0; aboveA = 0;
        for (int b = 511; b >= 0; b--) {
            if (c + hA[b] >= r) { selA = b; aboveA = c; break; }
            c += hA[b];
        }
    }
    __syncthreads();
    unsigned sA = selA;
    for (int i = t; i < 256; i += 512) hA[i] = 0;
    __syncthreads();
    for (unsigned i = t; i < n; i += 512) {
        unsigned b = cb[i];
        if (((b >> 8) & 0x1FF) == sA) atomicAdd(&hA[b & 0xFF], 1u);
    }
    __syncthreads();
    if (t == 0) {
        unsigned r2 = r - aboveA;
        unsigned c = 0; selB = 0; aboveB = 0;
        for (int b = 255; b >= 0; b--) {
            if (c + hA[b] >= r2) { selB = b; aboveB = c; break; }
            c += hA[b];
        }
    }
    __syncthreads();
    unsigned thr = (g_bin1[g] << 17) | (sA << 8) | selB;
    for (unsigned i = t; i < n; i += 512) {
        if (cb[i] == thr) {
            unsigned p = atomicAdd(&eqCnt, 1u);
            if (p < 64) eqIdx[p] = ci[i];
        }
    }
    __syncthreads();
    if (t == 0) {
        unsigned need = (r - aboveA) - aboveB;   // #ties to keep (>=1)
        unsigned m = min(eqCnt, 64u);
        unsigned cut = 0xFFFFFFFFu;
        if (need < m) {
            for (unsigned s = 0; s < need; s++) {
                unsigned best = 0xFFFFFFFFu; int bi = -1;
                for (unsigned i = 0; i < m; i++)
                    if (eqIdx[i] < best) { best = eqIdx[i]; bi = (int)i; }
                eqIdx[bi] = 0xFFFFFFFFu;
                cut = best;
            }
        }
        g_thr[g] = thr; g_cut[g] = cut;
    }
}

__device__ __forceinline__ bool keptf(unsigned bits, unsigned flat, unsigned thr, unsigned cut) {
    return (bits > thr) || (bits == thr && flat <= cut);
}

// ---------------- 5) degree: rowsum + colsum of kept entries ----------------
__global__ void k_deg(const float* __restrict__ adj) {
    int g = blockIdx.y;
    int warp = threadIdx.x >> 5, lane = threadIdx.x & 31;
    int row = blockIdx.x * 8 + warp;
    unsigned thr = g_thr[g], cut = g_cut[g];
    const float* a = adj + (size_t)g * NN + (size_t)row * NV;
    unsigned rowbase = (unsigned)row * NV;
    float rs = 0.f;
    for (int j = lane; j < NV; j += 32) {
        float v = a[j];
        unsigned b = __float_as_uint(v);
        if (keptf(b, rowbase + j, thr, cut)) {
            rs += v;
            atomicAdd(&g_colsum[g*NV + j], v);
        }
    }
    #pragma unroll
    for (int o = 16; o; o >>= 1) rs += __shfl_down_sync(0xFFFFFFFFu, rs, o);
    if (lane == 0) g_rowsum[g*NV + row] = rs;
}

__global__ void k_dinv() {
    int i = blockIdx.x * 256 + threadIdx.x;
    if (i < GG*NV) {
        float d = 0.5f * (g_rowsum[i] + g_colsum[i]);
        g_dinv[i] = d > 0.f ? rsqrtf(d) : 0.f;
    }
}

// ---------------- 6) norm_adj (upper-tri tiles, symmetric) + CSR build ----------------
// nm_ij = 0.5*(kept_ij*v_ij + kept_ji*v_ji) * dinv_i * dinv_j  ==  nm_ji (symmetric)
__global__ void k_norm(const float* __restrict__ adj, float* __restrict__ outA) {
    int g = blockIdx.y;
    int p = blockIdx.x;               // 528 = 32*33/2 tile pairs
    int bi = 0, rem = p;
    while (rem >= 32 - bi) { rem -= 32 - bi; bi++; }
    int bj = bi + rem;
    int i0 = bi * 32, j0 = bj * 32;
    __shared__ float T2[32][33];      // T2[r][c] = adj[j0+r][i0+c]
    __shared__ float NM[32][33];      // NM[ii][jj] = nm(i0+ii, j0+jj)
    const float* a = adj + (size_t)g * NN;
    int tx = threadIdx.x, ty = threadIdx.y;  // 32 x 8
    for (int rr = ty; rr < 32; rr += 8)
        T2[rr][tx] = a[(size_t)(j0 + rr) * NV + i0 + tx];
    __syncthreads();
    unsigned thr = g_thr[g], cut = g_cut[g];
    float dj = g_dinv[g*NV + j0 + tx];
    bool diag = (bi == bj);
    #pragma unroll
    for (int s = 0; s < 4; s++) {
        int ii = ty + 8 * s;
        int i = i0 + ii, j = j0 + tx;
        bool active = !diag || (tx >= ii);
        float vij = a[(size_t)i * NV + j];
        float vji = T2[tx][ii];
        float sum = 0.f;
        if (keptf(__float_as_uint(vij), (unsigned)(i*NV + j), thr, cut)) sum += vij;
        if (keptf(__float_as_uint(vji), (unsigned)(j*NV + i), thr, cut)) sum += vji;
        float nm = 0.5f * sum * g_dinv[g*NV + i] * dj;
        NM[ii][tx] = nm;
        if (active) {
            outA[(size_t)g * NN + (size_t)i * NV + j] = nm;
            if (nm != 0.f) {
                unsigned pos = atomicAdd(&g_rcnt[g*NV + i], 1u);
                if (pos < RCAP)
                    g_csr[((size_t)(g*NV + i)) * RCAP + pos] = make_float2(__uint_as_float((unsigned)j), nm);
                if (i != j) {
                    unsigned pos2 = atomicAdd(&g_rcnt[g*NV + j], 1u);
                    if (pos2 < RCAP)
                        g_csr[((size_t)(g*NV + j)) * RCAP + pos2] = make_float2(__uint_as_float((unsigned)i), nm);
                }
            }
        }
    }
    __syncthreads();
    if (!diag) {
        // transposed tile write: outA[j0+rr][i0+tx] = NM[tx][rr]
        #pragma unroll
        for (int s = 0; s < 4; s++) {
            int rr = ty + 8 * s;
            outA[(size_t)g * NN + (size_t)(j0 + rr) * NV + i0 + tx] = NM[tx][rr];
        }
    } else {
        // fill strictly-lower part of diagonal tile from symmetry
        #pragma unroll
        for (int s = 0; s < 4; s++) {
            int ii = ty + 8 * s;
            if (tx < ii)
                outA[(size_t)g * NN + (size_t)(i0 + ii) * NV + j0 + tx] = NM[tx][ii];
        }
    }
}

// ---------------- 7) y = x @ W  (flattened [G*N, F] @ [F, F]) ----------------
__global__ void k_y(const float* __restrict__ x, const float* __restrict__ Wm) {
    __shared__ float Xs[32][FF];
    int blk = blockIdx.x;           // 32 rows per block
    int t = threadIdx.x;            // 128 threads = output column
    const float* xr = x + (size_t)blk * 32 * FF;
    for (int i = t; i < 32 * FF; i += 128) Xs[i / FF][i % FF] = xr[i];
    __syncthreads();
    float acc[32];
    #pragma unroll
    for (int r = 0; r < 32; r++) acc[r] = 0.f;
    for (int k = 0; k < FF; k++) {
        float w = Wm[k * FF + t];
        #pragma unroll
        for (int r = 0; r < 32; r++) acc[r] += Xs[r][k] * w;
    }
    float* yo = g_y + (size_t)blk * 32 * FF;
    #pragma unroll
    for (int r = 0; r < 32; r++) yo[r * FF + t] = acc[r];
}

// ---------------- 8) fused SpMM + epilogue: h = gelu(norm@y + y + b) ----------------
// block = (g, 32-col feature chunk); y[:, f0:f0+32] staged in 128KB smem.
// warp-per-row: lane owns one feature column; CSR entries broadcast via shfl.
__global__ void __launch_bounds__(512) k_spmm(const float* __restrict__ bvec,
                                              float* __restrict__ outH) {
    extern __shared__ float ysm[];     // [1024][32]
    int g = blockIdx.y;
    int f0 = blockIdx.x * 32;
    const float* Y = g_y + (size_t)g * NV * FF;
    int tid = threadIdx.x;
    for (int idx = tid; idx < NV * 32; idx += 512) {
        int row = idx >> 5, f = idx & 31;
        ysm[idx] = Y[(size_t)row * FF + f0 + f];
    }
    __syncthreads();
    int warp = tid >> 5, lane = tid & 31;
    float bf = bvec[f0 + lane];
    int iEnd = warp * 64 + 64;
    for (int i = warp * 64; i < iEnd; i++) {
        unsigned len = min(g_rcnt[g*NV + i], (unsigned)RCAP);
        const float2* row = g_csr + ((size_t)(g*NV + i)) * RCAP;
        float acc = 0.f;
        for (unsigned base = 0; base < len; base += 32) {
            unsigned m = min(32u, len - base);
            float2 e = (base + lane < len) ? row[base + lane] : make_float2(0.f, 0.f);
            unsigned cl = __float_as_uint(e.x);
            for (unsigned t = 0; t < m; t++) {
                unsigned c = __shfl_sync(0xFFFFFFFFu, cl, t);
                float    v = __shfl_sync(0xFFFFFFFFu, e.y, t);
                acc += v * ysm[c * 32 + lane];
            }
        }
        float z = acc + ysm[i * 32 + lane] + bf;
        float h = 0.5f * z * (1.f + erff(z * 0.70710678118654752f));
        outH[((size_t)g * NV + i) * FF + f0 + lane] = h;
    }
}

// ---------------- launcher ----------------
extern "C" void kernel_launch(void* const* d_in, const int* in_sizes, int n_in,
                              void* d_out, int out_size) {
    const float* x   = (const float*)d_in[0];   // [8,4,1024,128]
    const float* adj = (const float*)d_in[1];   // [8,4,1024,1024]
    const float* Wm  = (const float*)d_in[2];   // [128,128]
    const float* bv  = (const float*)d_in[3];   // [128]
    float* outH = (float*)d_out;                         // gelu output, 4194304 floats
    float* outA = (float*)d_out + (size_t)GG * NV * FF;  // norm_adj copy, 33554432 floats

    // Idempotent, host-side, non-captured call — no static guard (harness rule).
    cudaFuncSetAttribute(k_spmm, cudaFuncAttributeMaxDynamicSharedMemorySize,
                         NV * 32 * (int)sizeof(float));

    void *p_hist, *p_colsum, *p_ccnt, *p_rcnt;
    cudaGetSymbolAddress(&p_hist, g_hist1);
    cudaGetSymbolAddress(&p_colsum, g_colsum);
    cudaGetSymbolAddress(&p_ccnt, g_cand_cnt);
    cudaGetSymbolAddress(&p_rcnt, g_rcnt);
    cudaMemsetAsync(p_hist, 0, sizeof(unsigned) * GG * NBINS);
    cudaMemsetAsync(p_colsum, 0, sizeof(float) * GG * NV);
    cudaMemsetAsync(p_ccnt, 0, sizeof(unsigned) * GG);
    cudaMemsetAsync(p_rcnt, 0, sizeof(unsigned) * GG * NV);

    k_hist<<<dim3(16, GG), 256>>>((const unsigned*)adj);
    k_scan<<<GG, 256>>>();
    k_collect<<<dim3(32, GG), 256>>>((const unsigned*)adj);
    k_select<<<GG, 512>>>();
    k_deg<<<dim3(NV / 8, GG), 256>>>(adj);
    k_dinv<<<(GG * NV + 255) / 256, 256>>>();
    k_norm<<<dim3(528, GG), dim3(32, 8)>>>(adj, outA);
    k_y<<<(GG * NV) / 32, 128>>>(x, Wm);
    k_spmm<<<dim3(FF / 32, GG), 512, NV * 32 * sizeof(float)>>>(bv, outH);
}

// round 6
// speedup vs baseline: 1.2463x; 1.0949x over previous
#include <cuda_runtime.h>
#include <math.h>

// Problem dims
#define GG 32          // B*H
#define NV 1024        // nodes
#define FF 128         // features = hidden
#define NN (NV*NV)
#define K_TOP 32768    // (N*N) // sqrt(N)
#define NBINS 8192
#define CAP 24576
#define RCAP 128       // padded CSR slots per row (avg ~64, huge margin)

// ---------------- scratch (device globals; no allocation allowed) ----------------
__device__ unsigned g_hist1[GG*NBINS];
__device__ unsigned g_bin1[GG];
__device__ unsigned g_above[GG];
__device__ unsigned g_cand_cnt[GG];
__device__ unsigned g_cand_bits[GG*CAP];
__device__ unsigned g_cand_idx[GG*CAP];
__device__ unsigned g_thr[GG];
__device__ unsigned g_cut[GG];
__device__ float    g_rowsum[GG*NV];
__device__ float    g_dinv[GG*NV];
__device__ float    g_y[(size_t)GG*NV*FF];         // y = x @ W  (16 MB)
__device__ unsigned g_rcnt[GG*NV];                 // nnz per row
__device__ float2   g_csr[(size_t)GG*NV*RCAP];     // (col-as-bits, s-val) 32 MB

// ---------------- 1) level-1 histogram over bits>>17 (uint4 reads) ----------------
__global__ void k_hist(const uint4* __restrict__ adj4) {
    __shared__ unsigned sh[NBINS];
    for (int i = threadIdx.x; i < NBINS; i += 256) sh[i] = 0;
    __syncthreads();
    int g = blockIdx.y;
    int slice = (NN / 4) / gridDim.x;
    const uint4* base = adj4 + (size_t)g * (NN / 4) + (size_t)blockIdx.x * slice;
    for (int i = threadIdx.x; i < slice; i += 256) {
        uint4 q = base[i];
        atomicAdd(&sh[q.x >> 17], 1u);
        atomicAdd(&sh[q.y >> 17], 1u);
        atomicAdd(&sh[q.z >> 17], 1u);
        atomicAdd(&sh[q.w >> 17], 1u);
    }
    __syncthreads();
    for (int i = threadIdx.x; i < NBINS; i += 256)
        if (sh[i]) atomicAdd(&g_hist1[g*NBINS + i], sh[i]);
}

// ---------------- 2) find bin containing k-th largest ----------------
__global__ void k_scan() {
    int g = blockIdx.x;
    int t = threadIdx.x;           // 256 threads, 32 bins each
    __shared__ unsigned ts[256];
    __shared__ int s_t;
    __shared__ unsigned s_excl;
    const unsigned* h = g_hist1 + g*NBINS;
    unsigned s = 0;
    for (int b = 0; b < 32; b++) s += h[t*32 + b];
    ts[t] = s;
    __syncthreads();
    if (t == 0) {
        unsigned c = 0;
        s_t = 0; s_excl = 0;
        for (int i = 255; i >= 0; i--) {
            if (c + ts[i] >= K_TOP) { s_t = i; s_excl = c; break; }
            c += ts[i];
        }
    }
    __syncthreads();
    if (t == s_t) {
        unsigned c = s_excl;
        for (int b = 31; b >= 0; b--) {
            unsigned hb = h[t*32 + b];
            if (c + hb >= K_TOP) { g_bin1[g] = t*32 + b; g_above[g] = c; break; }
            c += hb;
        }
    }
}

// ---------------- 3) collect candidates in the threshold bin (uint4 reads) ----------------
__global__ void k_collect(const uint4* __restrict__ adj4) {
    int g = blockIdx.y;
    unsigned bin1 = g_bin1[g];
    int slice = (NN / 4) / gridDim.x;
    unsigned start4 = blockIdx.x * slice;
    const uint4* base = adj4 + (size_t)g * (NN / 4);
    for (int i = threadIdx.x; i < slice; i += 256) {
        unsigned i4 = start4 + i;
        uint4 q = base[i4];
        unsigned v[4] = {q.x, q.y, q.z, q.w};
        #pragma unroll
        for (int c = 0; c < 4; c++) {
            if ((v[c] >> 17) == bin1) {
                unsigned p = atomicAdd(&g_cand_cnt[g], 1u);
                if (p < CAP) { g_cand_bits[g*CAP + p] = v[c]; g_cand_idx[g*CAP + p] = i4*4 + c; }
            }
        }
    }
}

// ---------------- 4) exact threshold bits + tie cutoff index ----------------
__global__ void k_select() {
    int g = blockIdx.x;
    int t = threadIdx.x;  // 512 threads
    unsigned n = min(g_cand_cnt[g], (unsigned)CAP);
    unsigned r = K_TOP - g_above[g];   // rank (1-based, largest-first) within the bin
    __shared__ unsigned hA[512];
    __shared__ unsigned selA, aboveA, selB, aboveB;
    __shared__ unsigned eqIdx[64];
    __shared__ unsigned eqCnt;
    const unsigned* cb = g_cand_bits + g*CAP;
    const unsigned* ci = g_cand_idx + g*CAP;

    for (int i = t; i < 512; i += 512) hA[i] = 0;
    if (t == 0) eqCnt = 0;
    __syncthreads();
    for (unsigned i = t; i < n; i += 512) atomicAdd(&hA[(cb[i] >> 8) & 0x1FF], 1u);
    __syncthreads();
    if (t == 0) {
        unsigned c = 0; selA = 0; aboveA = 0;
        for (int b = 511; b >= 0; b--) {
            if (c + hA[b] >= r) { selA = b; aboveA = c; break; }
            c += hA[b];
        }
    }
    __syncthreads();
    unsigned sA = selA;
    for (int i = t; i < 256; i += 512) hA[i] = 0;
    __syncthreads();
    for (unsigned i = t; i < n; i += 512) {
        unsigned b = cb[i];
        if (((b >> 8) & 0x1FF) == sA) atomicAdd(&hA[b & 0xFF], 1u);
    }
    __syncthreads();
    if (t == 0) {
        unsigned r2 = r - aboveA;
        unsigned c = 0; selB = 0; aboveB = 0;
        for (int b = 255; b >= 0; b--) {
            if (c + hA[b] >= r2) { selB = b; aboveB = c; break; }
            c += hA[b];
        }
    }
    __syncthreads();
    unsigned thr = (g_bin1[g] << 17) | (sA << 8) | selB;
    for (unsigned i = t; i < n; i += 512) {
        if (cb[i] == thr) {
            unsigned p = atomicAdd(&eqCnt, 1u);
            if (p < 64) eqIdx[p] = ci[i];
        }
    }
    __syncthreads();
    if (t == 0) {
        unsigned need = (r - aboveA) - aboveB;   // #ties to keep (>=1)
        unsigned m = min(eqCnt, 64u);
        unsigned cut = 0xFFFFFFFFu;
        if (need < m) {
            for (unsigned s = 0; s < need; s++) {
                unsigned best = 0xFFFFFFFFu; int bi = -1;
                for (unsigned i = 0; i < m; i++)
                    if (eqIdx[i] < best) { best = eqIdx[i]; bi = (int)i; }
                eqIdx[bi] = 0xFFFFFFFFu;
                cut = best;
            }
        }
        g_thr[g] = thr; g_cut[g] = cut;
    }
}

__device__ __forceinline__ bool keptf(unsigned bits, unsigned flat, unsigned thr, unsigned cut) {
    return (bits > thr) || (bits == thr && flat <= cut);
}

// ---------------- 5) fused degree + CSR build (one adj read, upper-tri tiles) ----------------
// s_ij = 0.5*(kept_ij*v_ij + kept_ji*v_ji) (symmetric). deg_i = sum_j s_ij.
__global__ void k_degcsr(const float* __restrict__ adj) {
    int g = blockIdx.y;
    int p = blockIdx.x;               // 528 = 32*33/2 tile pairs
    int bi = 0, rem = p;
    while (rem >= 32 - bi) { rem -= 32 - bi; bi++; }
    int bj = bi + rem;
    int i0 = bi * 32, j0 = bj * 32;
    bool diag = (bi == bj);
    __shared__ float T2[32][33];      // T2[r][c] = adj[j0+r][i0+c]
    __shared__ float rs[64];          // [0:32) rows i0.., [32:64) rows j0..
    const float* a = adj + (size_t)g * NN;
    int tx = threadIdx.x, ty = threadIdx.y;  // 32 x 8
    for (int rr = ty; rr < 32; rr += 8)
        T2[rr][tx] = a[(size_t)(j0 + rr) * NV + i0 + tx];
    if (ty < 2) rs[ty * 32 + tx] = 0.f;
    __syncthreads();
    unsigned thr = g_thr[g], cut = g_cut[g];
    #pragma unroll
    for (int s = 0; s < 4; s++) {
        int ii = ty + 8 * s;
        int i = i0 + ii, j = j0 + tx;
        bool active = !diag || (tx >= ii);
        if (active) {
            float vij = a[(size_t)i * NV + j];
            float vji = T2[tx][ii];
            float sum = 0.f;
            if (keptf(__float_as_uint(vij), (unsigned)(i*NV + j), thr, cut)) sum += vij;
            if (keptf(__float_as_uint(vji), (unsigned)(j*NV + i), thr, cut)) sum += vji;
            float sv = 0.5f * sum;
            if (sv != 0.f) {
                atomicAdd(&rs[ii], sv);
                unsigned pos = atomicAdd(&g_rcnt[g*NV + i], 1u);
                if (pos < RCAP)
                    g_csr[((size_t)(g*NV + i)) * RCAP + pos] = make_float2(__uint_as_float((unsigned)j), sv);
                if (i != j) {
                    atomicAdd(&rs[diag ? tx : (32 + tx)], sv);
                    unsigned pos2 = atomicAdd(&g_rcnt[g*NV + j], 1u);
                    if (pos2 < RCAP)
                        g_csr[((size_t)(g*NV + j)) * RCAP + pos2] = make_float2(__uint_as_float((unsigned)i), sv);
                }
            }
        }
    }
    __syncthreads();
    if (ty == 0) {
        if (rs[tx] != 0.f) atomicAdd(&g_rowsum[g*NV + i0 + tx], rs[tx]);
    } else if (ty == 1 && !diag) {
        if (rs[32 + tx] != 0.f) atomicAdd(&g_rowsum[g*NV + j0 + tx], rs[32 + tx]);
    }
}

__global__ void k_dinv() {
    int i = blockIdx.x * 256 + threadIdx.x;
    if (i < GG*NV) {
        float d = g_rowsum[i];
        g_dinv[i] = d > 0.f ? rsqrtf(d) : 0.f;
    }
}

// ---------------- 6) dense norm_adj from CSR (no adj re-read) ----------------
// block = 8 rows; scatter CSR into smem row buffers, stream out coalesced.
__global__ void __launch_bounds__(256) k_fill(float* __restrict__ outA) {
    __shared__ float buf[8 * NV];    // 32KB
    int gr = blockIdx.x;             // 4096 blocks
    int g = gr >> 7;
    int r0 = (gr & 127) * 8;
    int tid = threadIdx.x;
    float4* b4 = (float4*)buf;
    for (int i = tid; i < 8 * NV / 4; i += 256) b4[i] = make_float4(0.f, 0.f, 0.f, 0.f);
    __syncthreads();
    int warp = tid >> 5, lane = tid & 31;
    int i = r0 + warp;
    int gi = g * NV + i;
    float di = g_dinv[gi];
    unsigned len = min(g_rcnt[gi], (unsigned)RCAP);
    const float2* row = g_csr + (size_t)gi * RCAP;
    const float* dv = g_dinv + g * NV;
    for (unsigned l = lane; l < len; l += 32) {
        float2 e = row[l];
        unsigned c = __float_as_uint(e.x);
        buf[warp * NV + c] = di * e.y * dv[c];
    }
    __syncthreads();
    float4* dst = (float4*)(outA + (size_t)g * NN + (size_t)r0 * NV);
    for (int idx = tid; idx < 8 * NV / 4; idx += 256) dst[idx] = b4[idx];
}

// ---------------- 7) y = x @ W  (flattened [G*N, F] @ [F, F]) ----------------
__global__ void k_y(const float* __restrict__ x, const float* __restrict__ Wm) {
    __shared__ float Xs[32][FF];
    int blk = blockIdx.x;           // 32 rows per block
    int t = threadIdx.x;            // 128 threads = output column
    const float* xr = x + (size_t)blk * 32 * FF;
    for (int i = t; i < 32 * FF; i += 128) Xs[i / FF][i % FF] = xr[i];
    __syncthreads();
    float acc[32];
    #pragma unroll
    for (int r = 0; r < 32; r++) acc[r] = 0.f;
    for (int k = 0; k < FF; k++) {
        float w = Wm[k * FF + t];
        #pragma unroll
        for (int r = 0; r < 32; r++) acc[r] += Xs[r][k] * w;
    }
    float* yo = g_y + (size_t)blk * 32 * FF;
    #pragma unroll
    for (int r = 0; r < 32; r++) yo[r * FF + t] = acc[r];
}

// ---------------- 8) fused SpMM + epilogue: h = gelu(dinv_i*(S@(dinv.*y)) + y + b) ----------------
// block = (g, 32-col feature chunk). ysm = dinv_col * y staged in 128KB smem.
// warp-per-row; entries staged per-warp in smem; fixed 32-trip unrolled inner loop.
__global__ void __launch_bounds__(512) k_spmm(const float* __restrict__ bvec,
                                              float* __restrict__ outH) {
    extern __shared__ float smem_dyn[];
    float*  ysm  = smem_dyn;                      // [1024*32]
    float2* ebuf = (float2*)(smem_dyn + NV * 32); // [16 warps][32]
    int g = blockIdx.y;
    int f0 = blockIdx.x * 32;
    const float* Y = g_y + (size_t)g * NV * FF;
    const float* dv = g_dinv + g * NV;
    int tid = threadIdx.x;
    for (int idx = tid; idx < NV * 32; idx += 512) {
        int row = idx >> 5, f = idx & 31;
        ysm[idx] = Y[(size_t)row * FF + f0 + f] * dv[row];
    }
    __syncthreads();
    int warp = tid >> 5, lane = tid & 31;
    float2* eb = ebuf + warp * 32;
    float bf = bvec[f0 + lane];
    int iEnd = warp * 64 + 64;
    for (int i = warp * 64; i < iEnd; i++) {
        unsigned len = min(g_rcnt[g*NV + i], (unsigned)RCAP);
        const float2* row = g_csr + ((size_t)(g*NV + i)) * RCAP;
        float a0 = 0.f, a1 = 0.f, a2 = 0.f, a3 = 0.f;
        for (unsigned base = 0; base < len; base += 32) {
            eb[lane] = (base + lane < len) ? row[base + lane] : make_float2(0.f, 0.f);
            __syncwarp();
            #pragma unroll
            for (int t = 0; t < 32; t += 4) {
                float2 e0 = eb[t], e1 = eb[t+1], e2 = eb[t+2], e3 = eb[t+3];
                a0 += e0.y * ysm[__float_as_uint(e0.x) * 32 + lane];
                a1 += e1.y * ysm[__float_as_uint(e1.x) * 32 + lane];
                a2 += e2.y * ysm[__float_as_uint(e2.x) * 32 + lane];
                a3 += e3.y * ysm[__float_as_uint(e3.x) * 32 + lane];
            }
            __syncwarp();
        }
        float acc = (a0 + a1) + (a2 + a3);
        float yi = Y[(size_t)i * FF + f0 + lane];
        float z = dv[i] * acc + yi + bf;
        float h = 0.5f * z * (1.f + erff(z * 0.70710678118654752f));
        outH[((size_t)g * NV + i) * FF + f0 + lane] = h;
    }
}

// ---------------- launcher ----------------
extern "C" void kernel_launch(void* const* d_in, const int* in_sizes, int n_in,
                              void* d_out, int out_size) {
    const float* x   = (const float*)d_in[0];   // [8,4,1024,128]
    const float* adj = (const float*)d_in[1];   // [8,4,1024,1024]
    const float* Wm  = (const float*)d_in[2];   // [128,128]
    const float* bv  = (const float*)d_in[3];   // [128]
    float* outH = (float*)d_out;                         // gelu output, 4194304 floats
    float* outA = (float*)d_out + (size_t)GG * NV * FF;  // norm_adj copy, 33554432 floats

    // Idempotent host-side call (not captured); no static guard per harness rules.
    cudaFuncSetAttribute(k_spmm, cudaFuncAttributeMaxDynamicSharedMemorySize,
                         NV * 32 * (int)sizeof(float) + 16 * 32 * (int)sizeof(float2));

    void *p_hist, *p_rowsum, *p_ccnt, *p_rcnt;
    cudaGetSymbolAddress(&p_hist, g_hist1);
    cudaGetSymbolAddress(&p_rowsum, g_rowsum);
    cudaGetSymbolAddress(&p_ccnt, g_cand_cnt);
    cudaGetSymbolAddress(&p_rcnt, g_rcnt);
    cudaMemsetAsync(p_hist, 0, sizeof(unsigned) * GG * NBINS);
    cudaMemsetAsync(p_rowsum, 0, sizeof(float) * GG * NV);
    cudaMemsetAsync(p_ccnt, 0, sizeof(unsigned) * GG);
    cudaMemsetAsync(p_rcnt, 0, sizeof(unsigned) * GG * NV);

    k_hist<<<dim3(16, GG), 256>>>((const uint4*)adj);
    k_scan<<<GG, 256>>>();
    k_collect<<<dim3(32, GG), 256>>>((const uint4*)adj);
    k_select<<<GG, 512>>>();
    k_degcsr<<<dim3(528, GG), dim3(32, 8)>>>(adj);
    k_dinv<<<(GG * NV + 255) / 256, 256>>>();
    k_fill<<<GG * NV / 8, 256>>>(outA);
    k_y<<<(GG * NV) / 32, 128>>>(x, Wm);
    k_spmm<<<dim3(FF / 32, GG), 512,
             NV * 32 * sizeof(float) + 16 * 32 * sizeof(float2)>>>(bv, outH);
}